// round 2
// baseline (speedup 1.0000x reference)
#include <cuda_runtime.h>

#define N_ 20000
#define T_ 6890
#define F_ 128
#define KTOP 6
#define DEG 32
#define BR 64
#define BT 64
#define NTHREADS 128
#define QSPLIT 4
#define TILES_PER_Q 27               /* 4*27*64 = 6912 >= 6890 */
#define ROWBLOCKS ((N_ + BR - 1) / BR)

// ---------------- device scratch (no allocations allowed) ----------------
__device__ float g_tn[T_];
__device__ float g_partV[N_ * QSPLIT * KTOP];
__device__ int   g_partI[N_ * QSPLIT * KTOP];
__device__ float g_pred[N_ * 3];
__device__ float g_pm[N_ * 9];
__device__ float g_srcc[N_ * 3];
__device__ float g_tgtc[N_ * 3];

// ---------------- kernel 0: tn[j] = ||t_j||^2 ----------------
__global__ void tn_kernel(const float* __restrict__ tf) {
    int warp = (blockIdx.x * blockDim.x + threadIdx.x) >> 5;
    int lane = threadIdx.x & 31;
    if (warp >= T_) return;
    const float4* p = reinterpret_cast<const float4*>(tf + (size_t)warp * F_);
    float4 v = p[lane];
    float s = v.x * v.x + v.y * v.y + v.z * v.z + v.w * v.w;
#pragma unroll
    for (int o = 16; o; o >>= 1) s += __shfl_xor_sync(0xffffffffu, s, o);
    if (lane == 0) g_tn[warp] = s;
}

// ---------------- top-k helpers ----------------
__device__ __forceinline__ void insert6(float v, int idx, float tv[KTOP], int ti[KTOP]) {
    if (v <= tv[KTOP - 1]) return;
    float cv = v; int ci = idx;
#pragma unroll
    for (int q = 0; q < KTOP; q++) {
        if (cv > tv[q]) {
            float t1 = tv[q]; int t2 = ti[q];
            tv[q] = cv; ti[q] = ci;
            cv = t1; ci = t2;
        }
    }
}

struct TopkSmem {
    float4 sS[32][65];   // [k4][row]   64 rows x 128 feats
    float4 sT[32][65];   // [k4][col]   64 targets x 128 feats
    float  sVal[BR][67];
    float  sTn[BT];
    float  cV[BR][12];
    int    cI[BR][12];
};

// ---------------- kernel 1: tiled GEMM + streaming top-6 ----------------
// val[r][c] = 2 * dot(s_r, t_c) - ||t_c||^2  (== -dist + const(row))
__global__ __launch_bounds__(NTHREADS, 2) void topk_kernel(
    const float* __restrict__ S, const float* __restrict__ Tf) {
    extern __shared__ __align__(16) char smem_raw[];
    TopkSmem& sm = *reinterpret_cast<TopkSmem*>(smem_raw);

    const int tid  = threadIdx.x;
    const int rblk = blockIdx.x >> 2;
    const int q    = blockIdx.x & 3;
    const int rb   = rblk * BR;

    const float NINF = __int_as_float(0xff800000);
    const float PINF = __int_as_float(0x7f800000);

    // load source tile once
#pragma unroll
    for (int i = 0; i < 16; i++) {
        int idx = tid + i * NTHREADS;
        int r = idx >> 5, k4 = idx & 31;
        int gr = rb + r;
        float4 v = make_float4(0.f, 0.f, 0.f, 0.f);
        if (gr < N_) v = *reinterpret_cast<const float4*>(S + (size_t)gr * F_ + k4 * 4);
        sm.sS[k4][r] = v;
    }

    // per-thread streaming top-6 for one row (2 threads per row: even/odd cols)
    float tv[KTOP]; int ti[KTOP];
#pragma unroll
    for (int k = 0; k < KTOP; k++) { tv[k] = NINF; ti[k] = 0; }
    const int srow = tid >> 1;
    const int shalf = tid & 1;

    const int tcg = tid & 15;
    const int trg = tid >> 4;

    const int tile0 = q * TILES_PER_Q;
    for (int tile = tile0; tile < tile0 + TILES_PER_Q; tile++) {
        const int cb = tile * BT;
        // load target tile
#pragma unroll
        for (int i = 0; i < 16; i++) {
            int idx = tid + i * NTHREADS;
            int c = idx >> 5, k4 = idx & 31;
            int gc = cb + c;
            float4 v = make_float4(0.f, 0.f, 0.f, 0.f);
            if (gc < T_) v = *reinterpret_cast<const float4*>(Tf + (size_t)gc * F_ + k4 * 4);
            sm.sT[k4][c] = v;
        }
        if (tid < BT) {
            int gc = cb + tid;
            sm.sTn[tid] = (gc < T_) ? g_tn[gc] : PINF;
        }
        __syncthreads();   // (A)

        // 8 rows x 4 targets microtile
        float acc[8][4];
#pragma unroll
        for (int i = 0; i < 8; i++)
#pragma unroll
            for (int j = 0; j < 4; j++) acc[i][j] = 0.f;

#pragma unroll 8
        for (int k4 = 0; k4 < 32; k4++) {
            float4 b0 = sm.sT[k4][tcg];
            float4 b1 = sm.sT[k4][tcg + 16];
            float4 b2 = sm.sT[k4][tcg + 32];
            float4 b3 = sm.sT[k4][tcg + 48];
#pragma unroll
            for (int i = 0; i < 8; i++) {
                float4 a = sm.sS[k4][trg * 8 + i];
                acc[i][0] = fmaf(a.w, b0.w, fmaf(a.z, b0.z, fmaf(a.y, b0.y, fmaf(a.x, b0.x, acc[i][0]))));
                acc[i][1] = fmaf(a.w, b1.w, fmaf(a.z, b1.z, fmaf(a.y, b1.y, fmaf(a.x, b1.x, acc[i][1]))));
                acc[i][2] = fmaf(a.w, b2.w, fmaf(a.z, b2.z, fmaf(a.y, b2.y, fmaf(a.x, b2.x, acc[i][2]))));
                acc[i][3] = fmaf(a.w, b3.w, fmaf(a.z, b3.z, fmaf(a.y, b3.y, fmaf(a.x, b3.x, acc[i][3]))));
            }
        }

        // write val tile
#pragma unroll
        for (int i = 0; i < 8; i++)
#pragma unroll
            for (int j = 0; j < 4; j++) {
                int c = tcg + 16 * j;
                sm.sVal[trg * 8 + i][c] = 2.f * acc[i][j] - sm.sTn[c];
            }
        __syncthreads();   // (C)

        // scan: 2 threads per row, stride-2 columns
#pragma unroll 4
        for (int i2 = 0; i2 < 32; i2++) {
            int c = shalf + 2 * i2;
            float v = sm.sVal[srow][c];
            insert6(v, cb + c, tv, ti);
        }
        // next-tile load's barrier (A) protects sVal from rewrite
    }

    // in-block merge of the two half-lists per row, then write partials
#pragma unroll
    for (int k = 0; k < KTOP; k++) {
        sm.cV[srow][shalf * KTOP + k] = tv[k];
        sm.cI[srow][shalf * KTOP + k] = ti[k];
    }
    __syncthreads();
    if (tid < BR) {
        float bv[KTOP]; int bi[KTOP];
#pragma unroll
        for (int k = 0; k < KTOP; k++) { bv[k] = __int_as_float(0xff800000); bi[k] = 0; }
#pragma unroll
        for (int k = 0; k < 12; k++) insert6(sm.cV[tid][k], sm.cI[tid][k], bv, bi);
        int gr = rb + tid;
        if (gr < N_) {
            size_t base = ((size_t)gr * QSPLIT + q) * KTOP;
#pragma unroll
            for (int k = 0; k < KTOP; k++) {
                g_partV[base + k] = bv[k];
                g_partI[base + k] = bi[k];
            }
        }
    }
}

// ---------------- kernel 2: merge partial top-6, softmax, predicted ----------------
__global__ void merge_kernel(const float* __restrict__ TP) {
    int n = blockIdx.x * blockDim.x + threadIdx.x;
    if (n >= N_) return;
    float bv[KTOP]; int bi[KTOP];
#pragma unroll
    for (int k = 0; k < KTOP; k++) { bv[k] = __int_as_float(0xff800000); bi[k] = 0; }
    size_t base = (size_t)n * QSPLIT * KTOP;
#pragma unroll
    for (int k = 0; k < QSPLIT * KTOP; k++) insert6(g_partV[base + k], g_partI[base + k], bv, bi);

    float m = bv[0];
    float w[KTOP], sum = 0.f;
#pragma unroll
    for (int k = 0; k < KTOP; k++) { w[k] = expf(bv[k] - m); sum += w[k]; }
    float inv = 1.f / sum;
    float px = 0.f, py = 0.f, pz = 0.f;
#pragma unroll
    for (int k = 0; k < KTOP; k++) {
        float wk = w[k] * inv;
        const float* tp = TP + (size_t)bi[k] * 3;
        px = fmaf(wk, tp[0], px);
        py = fmaf(wk, tp[1], py);
        pz = fmaf(wk, tp[2], pz);
    }
    g_pred[n * 3 + 0] = px;
    g_pred[n * 3 + 1] = py;
    g_pred[n * 3 + 2] = pz;
}

// ---------------- kernel 3: per-node centers + covariance (warp/node) ----------------
__global__ void accum_kernel(const float* __restrict__ pos, const int* __restrict__ col) {
    int node = (blockIdx.x * blockDim.x + threadIdx.x) >> 5;
    int lane = threadIdx.x & 31;
    if (node >= N_) return;
    int c = col[node * DEG + lane];
    float sx = pos[c * 3 + 0], sy = pos[c * 3 + 1], sz = pos[c * 3 + 2];
    float tx = g_pred[c * 3 + 0], ty = g_pred[c * 3 + 1], tz = g_pred[c * 3 + 2];
    float v[15] = { sx, sy, sz, tx, ty, tz,
                    sx * tx, sx * ty, sx * tz,
                    sy * tx, sy * ty, sy * tz,
                    sz * tx, sz * ty, sz * tz };
#pragma unroll
    for (int k = 0; k < 15; k++)
#pragma unroll
        for (int o = 16; o; o >>= 1) v[k] += __shfl_xor_sync(0xffffffffu, v[k], o);
    if (lane == 0) {
        const float invd = 1.f / (float)DEG;
        float scx = v[0] * invd, scy = v[1] * invd, scz = v[2] * invd;
        float tcx = v[3] * invd, tcy = v[4] * invd, tcz = v[5] * invd;
        g_srcc[node * 3 + 0] = scx; g_srcc[node * 3 + 1] = scy; g_srcc[node * 3 + 2] = scz;
        g_tgtc[node * 3 + 0] = tcx; g_tgtc[node * 3 + 1] = tcy; g_tgtc[node * 3 + 2] = tcz;
        float sc[3] = { scx, scy, scz };
        float tc[3] = { tcx, tcy, tcz };
#pragma unroll
        for (int i = 0; i < 3; i++)
#pragma unroll
            for (int j = 0; j < 3; j++)
                g_pm[node * 9 + 3 * i + j] = v[6 + 3 * i + j] - (float)DEG * sc[i] * tc[j];
    }
}

// ---------------- kernel 4: 3x3 Procrustes SVD (thread/node, fp64 Jacobi) ----------------
__device__ __forceinline__ void jrot(double& mpp, double& mqq, double& mpq,
                                     double& mrp, double& mrq,
                                     double& v0p, double& v0q,
                                     double& v1p, double& v1q,
                                     double& v2p, double& v2q) {
    double apq = mpq;
    if (fabs(apq) < 1e-300) { mpq = 0.0; return; }
    double theta = (mqq - mpp) / (2.0 * apq);
    double t = copysign(1.0, theta) / (fabs(theta) + sqrt(1.0 + theta * theta));
    double c = 1.0 / sqrt(1.0 + t * t);
    double s = t * c;
    mpp -= t * apq; mqq += t * apq; mpq = 0.0;
    double x = mrp, y = mrq;
    mrp = c * x - s * y; mrq = s * x + c * y;
    double a, b;
    a = v0p; b = v0q; v0p = c * a - s * b; v0q = s * a + c * b;
    a = v1p; b = v1q; v1p = c * a - s * b; v1q = s * a + c * b;
    a = v2p; b = v2q; v2p = c * a - s * b; v2q = s * a + c * b;
}

__global__ void svd_kernel(float* __restrict__ outR, float* __restrict__ outT) {
    int n = blockIdx.x * blockDim.x + threadIdx.x;
    if (n >= N_) return;
    const float* pm = g_pm + (size_t)n * 9;
    double a00 = pm[0], a01 = pm[1], a02 = pm[2];
    double a10 = pm[3], a11 = pm[4], a12 = pm[5];
    double a20 = pm[6], a21 = pm[7], a22 = pm[8];

    // M = A^T A
    double m00 = a00 * a00 + a10 * a10 + a20 * a20;
    double m01 = a00 * a01 + a10 * a11 + a20 * a21;
    double m02 = a00 * a02 + a10 * a12 + a20 * a22;
    double m11 = a01 * a01 + a11 * a11 + a21 * a21;
    double m12 = a01 * a02 + a11 * a12 + a21 * a22;
    double m22 = a02 * a02 + a12 * a12 + a22 * a22;

    double v00 = 1, v01 = 0, v02 = 0;
    double v10 = 0, v11 = 1, v12 = 0;
    double v20 = 0, v21 = 0, v22 = 1;

#pragma unroll 1
    for (int sweep = 0; sweep < 6; sweep++) {
        jrot(m00, m11, m01, m02, m12, v00, v01, v10, v11, v20, v21); // (0,1) r=2
        jrot(m00, m22, m02, m01, m12, v00, v02, v10, v12, v20, v22); // (0,2) r=1
        jrot(m11, m22, m12, m01, m02, v01, v02, v11, v12, v21, v22); // (1,2) r=0
    }

    double e0 = m00, e1 = m11, e2 = m22;
    int i1 = 0; double eb = e0;
    if (e1 > eb) { i1 = 1; eb = e1; }
    if (e2 > eb) { i1 = 2; eb = e2; }
    int i3 = 0; double es = e0;
    if (e1 < es) { i3 = 1; es = e1; }
    if (e2 < es) { i3 = 2; es = e2; }
    if (i3 == i1) i3 = (i1 + 1) % 3;
    int i2 = 3 - i1 - i3;

    double v1x = (i1 == 0) ? v00 : ((i1 == 1) ? v01 : v02);
    double v1y = (i1 == 0) ? v10 : ((i1 == 1) ? v11 : v12);
    double v1z = (i1 == 0) ? v20 : ((i1 == 1) ? v21 : v22);
    double v2x = (i2 == 0) ? v00 : ((i2 == 1) ? v01 : v02);
    double v2y = (i2 == 0) ? v10 : ((i2 == 1) ? v11 : v12);
    double v2z = (i2 == 0) ? v20 : ((i2 == 1) ? v21 : v22);

    // u1 = A v1 / |A v1| ; u2 = orthonormalized A v2 ; u3 = u1 x u2 ; w3 = v1 x v2
    double u1x = a00 * v1x + a01 * v1y + a02 * v1z;
    double u1y = a10 * v1x + a11 * v1y + a12 * v1z;
    double u1z = a20 * v1x + a21 * v1y + a22 * v1z;
    double n1 = sqrt(u1x * u1x + u1y * u1y + u1z * u1z) + 1e-300;
    u1x /= n1; u1y /= n1; u1z /= n1;

    double u2x = a00 * v2x + a01 * v2y + a02 * v2z;
    double u2y = a10 * v2x + a11 * v2y + a12 * v2z;
    double u2z = a20 * v2x + a21 * v2y + a22 * v2z;
    double d12 = u1x * u2x + u1y * u2y + u1z * u2z;
    u2x -= d12 * u1x; u2y -= d12 * u1y; u2z -= d12 * u1z;
    double n2 = sqrt(u2x * u2x + u2y * u2y + u2z * u2z) + 1e-300;
    u2x /= n2; u2y /= n2; u2z /= n2;

    double u3x = u1y * u2z - u1z * u2y;
    double u3y = u1z * u2x - u1x * u2z;
    double u3z = u1x * u2y - u1y * u2x;
    double w3x = v1y * v2z - v1z * v2y;
    double w3y = v1z * v2x - v1x * v2z;
    double w3z = v1x * v2y - v1y * v2x;

    double R[3][3];
    double U1[3] = { u1x, u1y, u1z }, U2[3] = { u2x, u2y, u2z }, U3[3] = { u3x, u3y, u3z };
    double V1[3] = { v1x, v1y, v1z }, V2[3] = { v2x, v2y, v2z }, W3[3] = { w3x, w3y, w3z };
#pragma unroll
    for (int i = 0; i < 3; i++)
#pragma unroll
        for (int j = 0; j < 3; j++) {
            R[i][j] = U1[i] * V1[j] + U2[i] * V2[j] + U3[i] * W3[j];
            outR[(size_t)n * 9 + 3 * i + j] = (float)R[i][j];
        }

    double sc0 = g_srcc[n * 3 + 0], sc1 = g_srcc[n * 3 + 1], sc2 = g_srcc[n * 3 + 2];
    double tc0 = g_tgtc[n * 3 + 0], tc1 = g_tgtc[n * 3 + 1], tc2 = g_tgtc[n * 3 + 2];
    outT[(size_t)n * 3 + 0] = (float)(tc0 - (R[0][0] * sc0 + R[0][1] * sc1 + R[0][2] * sc2));
    outT[(size_t)n * 3 + 1] = (float)(tc1 - (R[1][0] * sc0 + R[1][1] * sc1 + R[1][2] * sc2));
    outT[(size_t)n * 3 + 2] = (float)(tc2 - (R[2][0] * sc0 + R[2][1] * sc1 + R[2][2] * sc2));
}

// ---------------- kernel 5: per-edge residual -> dst (warp/node) ----------------
// NOTE: reference uses the NEIGHBOR's transform: R[col], trans[col]
__global__ void dst_kernel(const float* __restrict__ pos, const int* __restrict__ col,
                           const float* __restrict__ R, const float* __restrict__ Tr,
                           float* __restrict__ dst) {
    int node = (blockIdx.x * blockDim.x + threadIdx.x) >> 5;
    int lane = threadIdx.x & 31;
    if (node >= N_) return;
    int c = col[node * DEG + lane];
    float sx = pos[c * 3 + 0], sy = pos[c * 3 + 1], sz = pos[c * 3 + 2];
    float tx = g_pred[c * 3 + 0], ty = g_pred[c * 3 + 1], tz = g_pred[c * 3 + 2];
    const float* r = R + (size_t)c * 9;    // neighbor's rotation
    const float* t = Tr + (size_t)c * 3;   // neighbor's translation
    float rx = r[0] * sx + r[1] * sy + r[2] * sz + t[0] - tx;
    float ry = r[3] * sx + r[4] * sy + r[5] * sz + t[1] - ty;
    float rz = r[6] * sx + r[7] * sy + r[8] * sz + t[2] - tz;
    float d = rx * rx + ry * ry + rz * rz;
#pragma unroll
    for (int o = 16; o; o >>= 1) d += __shfl_xor_sync(0xffffffffu, d, o);
    if (lane == 0) dst[node] = d * (1.f / (float)DEG);
}

// ---------------- launch ----------------
extern "C" void kernel_launch(void* const* d_in, const int* in_sizes, int n_in,
                              void* d_out, int out_size) {
    const float* S   = (const float*)d_in[0];   // source_feats [N,128]
    const float* Tf  = (const float*)d_in[1];   // target_feats [T,128]
    const float* TP  = (const float*)d_in[2];   // target_points [T,3]
    const float* pos = (const float*)d_in[3];   // pos [N,3]
    const int*   ei  = (const int*)d_in[4];     // edge_index [2,E]
    const int*   col = ei + (size_t)N_ * DEG;   // second row

    float* out   = (float*)d_out;
    float* outR  = out;                  // [N,3,3]
    float* outTr = out + (size_t)N_ * 9; // [N,3]
    float* outD  = out + (size_t)N_ * 12; // [N,1]

    cudaFuncSetAttribute(topk_kernel, cudaFuncAttributeMaxDynamicSharedMemorySize,
                         (int)sizeof(TopkSmem));

    tn_kernel<<<(T_ + 7) / 8, 256>>>(Tf);
    topk_kernel<<<ROWBLOCKS * QSPLIT, NTHREADS, sizeof(TopkSmem)>>>(S, Tf);
    merge_kernel<<<(N_ + 255) / 256, 256>>>(TP);
    accum_kernel<<<(N_ * DEG + 255) / 256, 256>>>(pos, col);
    svd_kernel<<<(N_ + 127) / 128, 128>>>(outR, outTr);
    dst_kernel<<<(N_ * DEG + 255) / 256, 256>>>(pos, col, outR, outTr, outD);
}